// round 11
// baseline (speedup 1.0000x reference)
#include <cuda_runtime.h>
#include <cuda_bf16.h>
#include <cuda_fp16.h>
#include <cstdint>

#define N_NODES 50000
#define N_EDGES 800000
#define SCAN_BLOCKS ((N_NODES + 255) / 256)   // 196
#define M_TILES (N_NODES / 16)                // 3125, exact

// ---------------- scratch (static __device__, zero-initialized at load) ----------------
__device__ float    g_Q[N_NODES * 128];
// interleaved fp16 K/V: per node 128 words; lane l owns words 4l..4l+3 = {K2l,K2l+1,V2l,V2l+1}
__device__ uint32_t g_KV[N_NODES * 128];
__device__ int      g_row_off[N_NODES + 1];
__device__ int      g_cnt[N_NODES];           // counts -> cursors; re-zeroed by aggregate
__device__ int      g_esrc[N_EDGES];          // src node id per CSR slot
__device__ int      g_part[SCAN_BLOCKS];

// bf16 split of h, packed 4 elems per uint2 (row-major halfword order)
__device__ uint2 g_hhi[N_NODES * 128 / 4];
__device__ uint2 g_hlo[N_NODES * 128 / 4];
// pre-swizzled weight fragments: [z][kstep][ntile][lane] -> {reg0, reg1} of mma B frag
__device__ uint2 g_wfhi[3][8][16][32];
__device__ uint2 g_wflo[3][8][16][32];

__device__ __forceinline__ uint32_t pack_bf2(__nv_bfloat16 a, __nv_bfloat16 b) {
    return (uint32_t)__bfloat16_as_ushort(a) | ((uint32_t)__bfloat16_as_ushort(b) << 16);
}

// ---------------- prep: z=0 split h, z=1 edge count, z=2 weight fragments ----------------
__global__ void __launch_bounds__(256) prep_kernel(
    const float* __restrict__ h, const int* __restrict__ dst,
    const float* __restrict__ Wq, const float* __restrict__ Wk, const float* __restrict__ Wv)
{
    const int z = blockIdx.z;
    const int tid = blockIdx.x * 256 + threadIdx.x;

    if (z == 0) {
        float4 v = *reinterpret_cast<const float4*>(&h[tid * 4]);
        __nv_bfloat16 h0 = __float2bfloat16_rn(v.x);
        __nv_bfloat16 h1 = __float2bfloat16_rn(v.y);
        __nv_bfloat16 h2 = __float2bfloat16_rn(v.z);
        __nv_bfloat16 h3 = __float2bfloat16_rn(v.w);
        uint2 hi, lo;
        hi.x = pack_bf2(h0, h1);
        hi.y = pack_bf2(h2, h3);
        lo.x = pack_bf2(__float2bfloat16_rn(v.x - __bfloat162float(h0)),
                        __float2bfloat16_rn(v.y - __bfloat162float(h1)));
        lo.y = pack_bf2(__float2bfloat16_rn(v.z - __bfloat162float(h2)),
                        __float2bfloat16_rn(v.w - __bfloat162float(h3)));
        g_hhi[tid] = hi;
        g_hlo[tid] = lo;
    } else if (z == 1) {
        if (tid < N_EDGES) atomicAdd(&g_cnt[dst[tid]], 1);
    } else {
        if (tid >= 3 * 8 * 16 * 32) return;
        int lane = tid & 31;
        int nt   = (tid >> 5) & 15;
        int ks   = (tid >> 9) & 7;
        int zz   = tid >> 12;
        const float* W = (zz == 0) ? Wq : (zz == 1) ? Wk : Wv;
        int g = lane >> 2, t = lane & 3;
        int n  = nt * 8 + g;
        int kb = ks * 16 + t * 2;
        float w0 = W[(kb + 0) * 128 + n];
        float w1 = W[(kb + 1) * 128 + n];
        float w2 = W[(kb + 8) * 128 + n];
        float w3 = W[(kb + 9) * 128 + n];
        __nv_bfloat16 b0 = __float2bfloat16_rn(w0);
        __nv_bfloat16 b1 = __float2bfloat16_rn(w1);
        __nv_bfloat16 b2 = __float2bfloat16_rn(w2);
        __nv_bfloat16 b3 = __float2bfloat16_rn(w3);
        uint2 hi, lo;
        hi.x = pack_bf2(b0, b1);
        hi.y = pack_bf2(b2, b3);
        lo.x = pack_bf2(__float2bfloat16_rn(w0 - __bfloat162float(b0)),
                        __float2bfloat16_rn(w1 - __bfloat162float(b1)));
        lo.y = pack_bf2(__float2bfloat16_rn(w2 - __bfloat162float(b2)),
                        __float2bfloat16_rn(w3 - __bfloat162float(b3)));
        g_wfhi[zz][ks][nt][lane] = hi;
        g_wflo[zz][ks][nt][lane] = lo;
    }
}

// ---------------- tensor-core GEMM (z=0) + CSR scatter (z=1), one launch ----------------
__device__ __forceinline__ void mma_bf16(float& c0, float& c1, float& c2, float& c3,
                                         uint32_t a0, uint32_t a1, uint32_t a2, uint32_t a3,
                                         uint32_t b0, uint32_t b1)
{
    asm volatile(
        "mma.sync.aligned.m16n8k16.row.col.f32.bf16.bf16.f32 "
        "{%0,%1,%2,%3},{%4,%5,%6,%7},{%8,%9},{%0,%1,%2,%3};"
        : "+f"(c0), "+f"(c1), "+f"(c2), "+f"(c3)
        : "r"(a0), "r"(a1), "r"(a2), "r"(a3), "r"(b0), "r"(b1));
}

// z=0: CTA = 16 m-rows x 128 n-cols x 3 weights (R9 configuration — best loads/MMA ratio).
//      __launch_bounds__(128, 4) caps regs at 128: kills ptxas's 288-deep B-load pipeline
//      (255 regs, occ 11.7%) while keeping the live set (~100 regs) spill-free.
// z=1: scatter — latency-bound, rides in gemm's idle issue/LSU slots.
__global__ void __launch_bounds__(128, 4) gemm_scatter(
    const float* __restrict__ bq, const float* __restrict__ bk, const float* __restrict__ bv,
    const int* __restrict__ src, const int* __restrict__ dst)
{
    if (blockIdx.z == 1) {
        // 3125 blocks * 128 threads = 400000 lanes; 2 strided edges each
        int tid = blockIdx.x * 128 + threadIdx.x;
        #pragma unroll
        for (int r = 0; r < 2; r++) {
            int e = tid + r * (M_TILES * 128);
            int p = atomicAdd(&g_cnt[dst[e]], 1);
            g_esrc[p] = src[e];
        }
        return;
    }

    const int m0   = blockIdx.x * 16;
    const int w    = threadIdx.x >> 5;
    const int lane = threadIdx.x & 31;
    const int g    = lane >> 2;
    const int t    = lane & 3;

    float c[3][4][4];
    #pragma unroll
    for (int z = 0; z < 3; z++) {
        const float* bias = (z == 0) ? bq : (z == 1) ? bk : bv;
        #pragma unroll
        for (int nt = 0; nt < 4; nt++) {
            int col = (w * 4 + nt) * 8 + t * 2;
            float b0 = bias[col], b1 = bias[col + 1];
            c[z][nt][0] = b0; c[z][nt][1] = b1;
            c[z][nt][2] = b0; c[z][nt][3] = b1;
        }
    }

    const uint32_t* Ahi = reinterpret_cast<const uint32_t*>(g_hhi);
    const uint32_t* Alo = reinterpret_cast<const uint32_t*>(g_hlo);
    const int rowA = m0 + g;                 // 64 words per row

    #pragma unroll
    for (int pass = 0; pass < 3; pass++) {
        const uint32_t* A = (pass == 2) ? Alo : Ahi;
        const bool useLo = (pass == 1);
        #pragma unroll
        for (int ks = 0; ks < 8; ks++) {
            int kw = ks * 8 + t;
            uint32_t a0 = A[rowA * 64 + kw];
            uint32_t a1 = A[(rowA + 8) * 64 + kw];
            uint32_t a2 = A[rowA * 64 + kw + 4];
            uint32_t a3 = A[(rowA + 8) * 64 + kw + 4];
            #pragma unroll
            for (int z = 0; z < 3; z++) {
                #pragma unroll
                for (int nt = 0; nt < 4; nt++) {
                    uint2 b = useLo ? g_wflo[z][ks][w * 4 + nt][lane]
                                    : g_wfhi[z][ks][w * 4 + nt][lane];
                    mma_bf16(c[z][nt][0], c[z][nt][1], c[z][nt][2], c[z][nt][3],
                             a0, a1, a2, a3, b.x, b.y);
                }
            }
        }
    }

    #pragma unroll
    for (int nt = 0; nt < 4; nt++) {
        int col = (w * 4 + nt) * 8 + t * 2;
        // Q fp32
        *reinterpret_cast<float2*>(&g_Q[(m0 + g) * 128 + col])     = make_float2(c[0][nt][0], c[0][nt][1]);
        *reinterpret_cast<float2*>(&g_Q[(m0 + g + 8) * 128 + col]) = make_float2(c[0][nt][2], c[0][nt][3]);
        // K, V fp16 interleaved: word index j = col/2 -> slot (j>>1)*4 + (j&1) (+2 for V)
        __half2 klo = __floats2half2_rn(c[1][nt][0], c[1][nt][1]);
        __half2 khi = __floats2half2_rn(c[1][nt][2], c[1][nt][3]);
        __half2 vlo = __floats2half2_rn(c[2][nt][0], c[2][nt][1]);
        __half2 vhi = __floats2half2_rn(c[2][nt][2], c[2][nt][3]);
        int j = col / 2;
        int slot = (j >> 1) * 4 + (j & 1);
        g_KV[(m0 + g) * 128 + slot]         = *reinterpret_cast<uint32_t*>(&klo);
        g_KV[(m0 + g + 8) * 128 + slot]     = *reinterpret_cast<uint32_t*>(&khi);
        g_KV[(m0 + g) * 128 + slot + 2]     = *reinterpret_cast<uint32_t*>(&vlo);
        g_KV[(m0 + g + 8) * 128 + slot + 2] = *reinterpret_cast<uint32_t*>(&vhi);
    }
}

// ---------------- parallel scan, stage 1 ----------------
__global__ void __launch_bounds__(256) scan_part_kernel()
{
    __shared__ int ws[8];
    int gid = blockIdx.x * 256 + threadIdx.x;
    int v = (gid < N_NODES) ? g_cnt[gid] : 0;
    int s = __reduce_add_sync(0xffffffffu, v);
    if ((threadIdx.x & 31) == 0) ws[threadIdx.x >> 5] = s;
    __syncthreads();
    if (threadIdx.x == 0) {
        int tot = 0;
        #pragma unroll
        for (int j = 0; j < 8; j++) tot += ws[j];
        g_part[blockIdx.x] = tot;
    }
}

// ---------------- parallel scan, stage 2 ----------------
__global__ void __launch_bounds__(256) scan_final_kernel()
{
    __shared__ int ps[8];
    __shared__ int ws[8];
    const int t = threadIdx.x, b = blockIdx.x;
    const int lane = t & 31, w = t >> 5;

    int pv = (t < b) ? g_part[t] : 0;
    int psum = __reduce_add_sync(0xffffffffu, pv);
    if (lane == 0) ps[w] = psum;
    __syncthreads();
    int offset = 0;
    #pragma unroll
    for (int j = 0; j < 8; j++) offset += ps[j];

    int gid = b * 256 + t;
    int c = (gid < N_NODES) ? g_cnt[gid] : 0;
    int incl = c;
    #pragma unroll
    for (int d = 1; d < 32; d <<= 1) {
        int u = __shfl_up_sync(0xffffffffu, incl, d);
        if (lane >= d) incl += u;
    }
    if (lane == 31) ws[w] = incl;
    __syncthreads();
    int woff = 0;
    #pragma unroll
    for (int j = 0; j < 8; j++) woff += (j < w) ? ws[j] : 0;

    int excl = offset + woff + incl - c;
    if (gid < N_NODES) {
        g_row_off[gid] = excl;
        g_cnt[gid]     = excl;           // cursor for scatter
    }
    if (gid == N_NODES - 1)
        g_row_off[N_NODES] = excl + c;
}

// ---------------- aggregation: one warp per dst node, 2-edge software pipeline ----------------
// lane l owns columns 4l..4l+3; each 4-lane quad owns one head (D=16).
__global__ void __launch_bounds__(256) aggregate_kernel(float* __restrict__ out)
{
    int warp = (blockIdx.x * blockDim.x + threadIdx.x) >> 5;
    int lane = threadIdx.x & 31;
    if (warp >= N_NODES) return;
    const int node = warp;

    const float4 q = *reinterpret_cast<const float4*>(&g_Q[node * 128 + lane * 4]);
    float4 acc0 = make_float4(0.f, 0.f, 0.f, 0.f);
    float4 acc1 = make_float4(0.f, 0.f, 0.f, 0.f);
    float  zz0 = 0.f, zz1 = 0.f;

    const int beg = g_row_off[node];
    const int end = g_row_off[node + 1];
    int i = beg;

    for (; i + 2 <= end; i += 2) {
        int s0 = g_esrc[i];
        int s1 = g_esrc[i + 1];
        uint4 kv0 = *reinterpret_cast<const uint4*>(&g_KV[s0 * 128 + lane * 4]);
        uint4 kv1 = *reinterpret_cast<const uint4*>(&g_KV[s1 * 128 + lane * 4]);

        float2 k0a = __half22float2(*reinterpret_cast<__half2*>(&kv0.x));
        float2 k0b = __half22float2(*reinterpret_cast<__half2*>(&kv0.y));
        float2 k1a = __half22float2(*reinterpret_cast<__half2*>(&kv1.x));
        float2 k1b = __half22float2(*reinterpret_cast<__half2*>(&kv1.y));

        float p0 = q.x * k0a.x + q.y * k0a.y + q.z * k0b.x + q.w * k0b.y;
        float p1 = q.x * k1a.x + q.y * k1a.y + q.z * k1b.x + q.w * k1b.y;
        p0 += __shfl_xor_sync(0xffffffffu, p0, 1);
        p1 += __shfl_xor_sync(0xffffffffu, p1, 1);
        p0 += __shfl_xor_sync(0xffffffffu, p0, 2);
        p1 += __shfl_xor_sync(0xffffffffu, p1, 2);

        float w0 = __expf(fminf(fmaxf(p0 * 0.25f, -5.f), 5.f));
        float w1 = __expf(fminf(fmaxf(p1 * 0.25f, -5.f), 5.f));

        float2 v0a = __half22float2(*reinterpret_cast<__half2*>(&kv0.z));
        float2 v0b = __half22float2(*reinterpret_cast<__half2*>(&kv0.w));
        float2 v1a = __half22float2(*reinterpret_cast<__half2*>(&kv1.z));
        float2 v1b = __half22float2(*reinterpret_cast<__half2*>(&kv1.w));

        acc0.x += v0a.x * w0;  acc0.y += v0a.y * w0;
        acc0.z += v0b.x * w0;  acc0.w += v0b.y * w0;
        acc1.x += v1a.x * w1;  acc1.y += v1a.y * w1;
        acc1.z += v1b.x * w1;  acc1.w += v1b.y * w1;
        zz0 += w0;
        zz1 += w1;
    }

    if (i < end) {
        int s = g_esrc[i];
        uint4 kv = *reinterpret_cast<const uint4*>(&g_KV[s * 128 + lane * 4]);
        float2 ka = __half22float2(*reinterpret_cast<__half2*>(&kv.x));
        float2 kb = __half22float2(*reinterpret_cast<__half2*>(&kv.y));
        float p = q.x * ka.x + q.y * ka.y + q.z * kb.x + q.w * kb.y;
        p += __shfl_xor_sync(0xffffffffu, p, 1);
        p += __shfl_xor_sync(0xffffffffu, p, 2);
        float wgt = __expf(fminf(fmaxf(p * 0.25f, -5.f), 5.f));
        float2 va = __half22float2(*reinterpret_cast<__half2*>(&kv.z));
        float2 vb = __half22float2(*reinterpret_cast<__half2*>(&kv.w));
        acc0.x += va.x * wgt;  acc0.y += va.y * wgt;
        acc0.z += vb.x * wgt;  acc0.w += vb.y * wgt;
        zz0 += wgt;
    }

    float inv = 1.f / (zz0 + zz1 + 1e-6f);
    float4 o = make_float4((acc0.x + acc1.x) * inv, (acc0.y + acc1.y) * inv,
                           (acc0.z + acc1.z) * inv, (acc0.w + acc1.w) * inv);
    *reinterpret_cast<float4*>(&out[node * 128 + lane * 4]) = o;

    if (lane == 0) g_cnt[node] = 0;                 // restore invariant for next launch
}

// ---------------- launch ----------------
extern "C" void kernel_launch(void* const* d_in, const int* in_sizes, int n_in,
                              void* d_out, int out_size)
{
    const float* h   = (const float*)d_in[0];
    // d_in[1] (e), d_in[8] (We), d_in[9] (be) are unused by the reference output.
    const int*   src = (const int*)d_in[2];
    const int*   dst = (const int*)d_in[3];
    const float* Wq  = (const float*)d_in[4];
    const float* bq  = (const float*)d_in[5];
    const float* Wk  = (const float*)d_in[6];
    const float* bk  = (const float*)d_in[7];
    const float* Wv  = (const float*)d_in[10];
    const float* bv  = (const float*)d_in[11];
    float* out = (float*)d_out;

    dim3 prep_grid(6250, 1, 3);    // z=0: h split, z=1: edge count, z=2: W frags
    prep_kernel<<<prep_grid, 256>>>(h, dst, Wq, Wk, Wv);

    scan_part_kernel<<<SCAN_BLOCKS, 256>>>();
    scan_final_kernel<<<SCAN_BLOCKS, 256>>>();

    dim3 gs_grid(M_TILES, 1, 2);   // z=0: gemm tiles, z=1: scatter (hidden under gemm)
    gemm_scatter<<<gs_grid, 128>>>(bq, bk, bv, src, dst);

    int agg_blocks = (N_NODES + 7) / 8;   // 8 warps (nodes) per 256-thread block
    aggregate_kernel<<<agg_blocks, 256>>>(out);
}

// round 12
// speedup vs baseline: 1.6422x; 1.6422x over previous
#include <cuda_runtime.h>
#include <cuda_bf16.h>
#include <cuda_fp16.h>
#include <cstdint>

#define N_NODES 50000
#define N_EDGES 800000
#define SCAN_BLOCKS ((N_NODES + 255) / 256)   // 196
#define M_TILES (N_NODES / 16)                // 3125, exact

// ---------------- scratch (static __device__, zero-initialized at load) ----------------
__device__ float    g_Q[N_NODES * 128];
// interleaved fp16 K/V: per node 128 words; lane l owns words 4l..4l+3 = {K2l,K2l+1,V2l,V2l+1}
__device__ uint32_t g_KV[N_NODES * 128];
__device__ int      g_row_off[N_NODES + 1];
__device__ int      g_cnt[N_NODES];           // counts -> cursors; re-zeroed by aggregate
__device__ int      g_esrc[N_EDGES];          // src node id per CSR slot
__device__ int      g_part[SCAN_BLOCKS];

// A fragments, pre-swizzled: [mtile][ks][lane] -> uint4 {a0,a1,a2,a3} mma A frag (bf16x2 words)
__device__ uint4 g_hfhi[M_TILES * 8 * 32];
__device__ uint4 g_hflo[M_TILES * 8 * 32];
// B fragments, paired: [z][ks][w][lane][pair] -> uint4 {nt_even.b0, nt_even.b1, nt_odd.b0, nt_odd.b1}
__device__ uint4 g_wfhi4[3][8][4][32][2];
__device__ uint4 g_wflo4[3][8][4][32][2];

__device__ __forceinline__ uint32_t pack_bf2(__nv_bfloat16 a, __nv_bfloat16 b) {
    return (uint32_t)__bfloat16_as_ushort(a) | ((uint32_t)__bfloat16_as_ushort(b) << 16);
}
__device__ __forceinline__ uint32_t split_hi(float x, float y, float& rx, float& ry) {
    __nv_bfloat16 bx = __float2bfloat16_rn(x), by = __float2bfloat16_rn(y);
    rx = x - __bfloat162float(bx);
    ry = y - __bfloat162float(by);
    return pack_bf2(bx, by);
}

// ---------------- prep: z=0 A-fragment split of h, z=1 edge count, z=2 B fragments ----------------
// grid (3125, 1, 3) x 256 threads
__global__ void __launch_bounds__(256) prep_kernel(
    const float* __restrict__ h, const int* __restrict__ dst,
    const float* __restrict__ Wq, const float* __restrict__ Wk, const float* __restrict__ Wv)
{
    const int z = blockIdx.z;
    const int tid = blockIdx.x * 256 + threadIdx.x;   // < 800000

    if (z == 0) {
        // tid -> (mtile, ks, lane); emit one uint4 A-frag (hi & lo) each
        int lane = tid & 31;
        int ks   = (tid >> 5) & 7;
        int mt   = tid >> 8;                 // < 3125
        int g = lane >> 2, t = lane & 3;
        int r0 = mt * 16 + g;
        int r1 = r0 + 8;
        int base = ks * 16 + 2 * t;
        float2 f0 = *reinterpret_cast<const float2*>(&h[r0 * 128 + base]);       // a0
        float2 f2 = *reinterpret_cast<const float2*>(&h[r0 * 128 + base + 8]);   // a2
        float2 f1 = *reinterpret_cast<const float2*>(&h[r1 * 128 + base]);       // a1
        float2 f3 = *reinterpret_cast<const float2*>(&h[r1 * 128 + base + 8]);   // a3
        uint4 hi, lo;
        float rx, ry;
        hi.x = split_hi(f0.x, f0.y, rx, ry); lo.x = pack_bf2(__float2bfloat16_rn(rx), __float2bfloat16_rn(ry));
        hi.y = split_hi(f1.x, f1.y, rx, ry); lo.y = pack_bf2(__float2bfloat16_rn(rx), __float2bfloat16_rn(ry));
        hi.z = split_hi(f2.x, f2.y, rx, ry); lo.z = pack_bf2(__float2bfloat16_rn(rx), __float2bfloat16_rn(ry));
        hi.w = split_hi(f3.x, f3.y, rx, ry); lo.w = pack_bf2(__float2bfloat16_rn(rx), __float2bfloat16_rn(ry));
        g_hfhi[tid] = hi;
        g_hflo[tid] = lo;
    } else if (z == 1) {
        if (tid < N_EDGES) atomicAdd(&g_cnt[dst[tid]], 1);
    } else {
        if (tid >= 3 * 8 * 16 * 32) return;
        int lane = tid & 31;
        int nt   = (tid >> 5) & 15;
        int ks   = (tid >> 9) & 7;
        int zz   = tid >> 12;
        const float* W = (zz == 0) ? Wq : (zz == 1) ? Wk : Wv;
        int g = lane >> 2, t = lane & 3;
        int n  = nt * 8 + g;
        int kb = ks * 16 + t * 2;
        float w0 = W[(kb + 0) * 128 + n];
        float w1 = W[(kb + 1) * 128 + n];
        float w2 = W[(kb + 8) * 128 + n];
        float w3 = W[(kb + 9) * 128 + n];
        __nv_bfloat16 b0 = __float2bfloat16_rn(w0);
        __nv_bfloat16 b1 = __float2bfloat16_rn(w1);
        __nv_bfloat16 b2 = __float2bfloat16_rn(w2);
        __nv_bfloat16 b3 = __float2bfloat16_rn(w3);
        uint2 hi, lo;
        hi.x = pack_bf2(b0, b1);
        hi.y = pack_bf2(b2, b3);
        lo.x = pack_bf2(__float2bfloat16_rn(w0 - __bfloat162float(b0)),
                        __float2bfloat16_rn(w1 - __bfloat162float(b1)));
        lo.y = pack_bf2(__float2bfloat16_rn(w2 - __bfloat162float(b2)),
                        __float2bfloat16_rn(w3 - __bfloat162float(b3)));
        int w = nt >> 2, p = (nt >> 1) & 1, which = nt & 1;
        reinterpret_cast<uint2*>(&g_wfhi4[zz][ks][w][lane][p])[which] = hi;
        reinterpret_cast<uint2*>(&g_wflo4[zz][ks][w][lane][p])[which] = lo;
    }
}

// ---------------- tensor-core GEMM (z=0) + CSR scatter (z=1), one launch ----------------
__device__ __forceinline__ void mma_bf16(float& c0, float& c1, float& c2, float& c3,
                                         uint32_t a0, uint32_t a1, uint32_t a2, uint32_t a3,
                                         uint32_t b0, uint32_t b1)
{
    asm volatile(
        "mma.sync.aligned.m16n8k16.row.col.f32.bf16.bf16.f32 "
        "{%0,%1,%2,%3},{%4,%5,%6,%7},{%8,%9},{%0,%1,%2,%3};"
        : "+f"(c0), "+f"(c1), "+f"(c2), "+f"(c3)
        : "r"(a0), "r"(a1), "r"(a2), "r"(a3), "r"(b0), "r"(b1));
}

// z=0: CTA = 16 m-rows x 128 n-cols x 3 weights. All loads are LDG.128 fragment loads:
//      1 A + 6 B per (pass,ks) = 168 LDGs/warp total (was 384). Natural regs (no cap).
// z=1: scatter — latency-bound, rides in gemm's idle issue/LSU slots.
__global__ void __launch_bounds__(128) gemm_scatter(
    const float* __restrict__ bq, const float* __restrict__ bk, const float* __restrict__ bv,
    const int* __restrict__ src, const int* __restrict__ dst)
{
    if (blockIdx.z == 1) {
        int tid = blockIdx.x * 128 + threadIdx.x;
        #pragma unroll
        for (int r = 0; r < 2; r++) {
            int e = tid + r * (M_TILES * 128);
            int p = atomicAdd(&g_cnt[dst[e]], 1);
            g_esrc[p] = src[e];
        }
        return;
    }

    const int m0   = blockIdx.x * 16;
    const int w    = threadIdx.x >> 5;
    const int lane = threadIdx.x & 31;
    const int g    = lane >> 2;
    const int t    = lane & 3;

    float c[3][4][4];
    #pragma unroll
    for (int z = 0; z < 3; z++) {
        const float* bias = (z == 0) ? bq : (z == 1) ? bk : bv;
        #pragma unroll
        for (int nt = 0; nt < 4; nt++) {
            int col = (w * 4 + nt) * 8 + t * 2;
            float b0 = bias[col], b1 = bias[col + 1];
            c[z][nt][0] = b0; c[z][nt][1] = b1;
            c[z][nt][2] = b0; c[z][nt][3] = b1;
        }
    }

    const int afrag_base = blockIdx.x * 8 * 32 + lane;   // + ks*32

    #pragma unroll
    for (int pass = 0; pass < 3; pass++) {
        const uint4* Af = (pass == 2) ? g_hflo : g_hfhi;
        const bool useLo = (pass == 1);
        #pragma unroll
        for (int ks = 0; ks < 8; ks++) {
            uint4 a = Af[afrag_base + ks * 32];
            #pragma unroll
            for (int z = 0; z < 3; z++) {
                uint4 bp0 = useLo ? g_wflo4[z][ks][w][lane][0] : g_wfhi4[z][ks][w][lane][0];
                uint4 bp1 = useLo ? g_wflo4[z][ks][w][lane][1] : g_wfhi4[z][ks][w][lane][1];
                mma_bf16(c[z][0][0], c[z][0][1], c[z][0][2], c[z][0][3],
                         a.x, a.y, a.z, a.w, bp0.x, bp0.y);
                mma_bf16(c[z][1][0], c[z][1][1], c[z][1][2], c[z][1][3],
                         a.x, a.y, a.z, a.w, bp0.z, bp0.w);
                mma_bf16(c[z][2][0], c[z][2][1], c[z][2][2], c[z][2][3],
                         a.x, a.y, a.z, a.w, bp1.x, bp1.y);
                mma_bf16(c[z][3][0], c[z][3][1], c[z][3][2], c[z][3][3],
                         a.x, a.y, a.z, a.w, bp1.z, bp1.w);
            }
        }
    }

    #pragma unroll
    for (int nt = 0; nt < 4; nt++) {
        int col = (w * 4 + nt) * 8 + t * 2;
        // Q fp32
        *reinterpret_cast<float2*>(&g_Q[(m0 + g) * 128 + col])     = make_float2(c[0][nt][0], c[0][nt][1]);
        *reinterpret_cast<float2*>(&g_Q[(m0 + g + 8) * 128 + col]) = make_float2(c[0][nt][2], c[0][nt][3]);
        // K, V fp16 interleaved: word index j = col/2 -> slot (j>>1)*4 + (j&1) (+2 for V)
        __half2 klo = __floats2half2_rn(c[1][nt][0], c[1][nt][1]);
        __half2 khi = __floats2half2_rn(c[1][nt][2], c[1][nt][3]);
        __half2 vlo = __floats2half2_rn(c[2][nt][0], c[2][nt][1]);
        __half2 vhi = __floats2half2_rn(c[2][nt][2], c[2][nt][3]);
        int j = col / 2;
        int slot = (j >> 1) * 4 + (j & 1);
        g_KV[(m0 + g) * 128 + slot]         = *reinterpret_cast<uint32_t*>(&klo);
        g_KV[(m0 + g + 8) * 128 + slot]     = *reinterpret_cast<uint32_t*>(&khi);
        g_KV[(m0 + g) * 128 + slot + 2]     = *reinterpret_cast<uint32_t*>(&vlo);
        g_KV[(m0 + g + 8) * 128 + slot + 2] = *reinterpret_cast<uint32_t*>(&vhi);
    }
}

// ---------------- parallel scan, stage 1 ----------------
__global__ void __launch_bounds__(256) scan_part_kernel()
{
    __shared__ int ws[8];
    int gid = blockIdx.x * 256 + threadIdx.x;
    int v = (gid < N_NODES) ? g_cnt[gid] : 0;
    int s = __reduce_add_sync(0xffffffffu, v);
    if ((threadIdx.x & 31) == 0) ws[threadIdx.x >> 5] = s;
    __syncthreads();
    if (threadIdx.x == 0) {
        int tot = 0;
        #pragma unroll
        for (int j = 0; j < 8; j++) tot += ws[j];
        g_part[blockIdx.x] = tot;
    }
}

// ---------------- parallel scan, stage 2 ----------------
__global__ void __launch_bounds__(256) scan_final_kernel()
{
    __shared__ int ps[8];
    __shared__ int ws[8];
    const int t = threadIdx.x, b = blockIdx.x;
    const int lane = t & 31, w = t >> 5;

    int pv = (t < b) ? g_part[t] : 0;
    int psum = __reduce_add_sync(0xffffffffu, pv);
    if (lane == 0) ps[w] = psum;
    __syncthreads();
    int offset = 0;
    #pragma unroll
    for (int j = 0; j < 8; j++) offset += ps[j];

    int gid = b * 256 + t;
    int c = (gid < N_NODES) ? g_cnt[gid] : 0;
    int incl = c;
    #pragma unroll
    for (int d = 1; d < 32; d <<= 1) {
        int u = __shfl_up_sync(0xffffffffu, incl, d);
        if (lane >= d) incl += u;
    }
    if (lane == 31) ws[w] = incl;
    __syncthreads();
    int woff = 0;
    #pragma unroll
    for (int j = 0; j < 8; j++) woff += (j < w) ? ws[j] : 0;

    int excl = offset + woff + incl - c;
    if (gid < N_NODES) {
        g_row_off[gid] = excl;
        g_cnt[gid]     = excl;           // cursor for scatter
    }
    if (gid == N_NODES - 1)
        g_row_off[N_NODES] = excl + c;
}

// ---------------- aggregation: one warp per dst node, 2-edge software pipeline ----------------
// lane l owns columns 4l..4l+3; each 4-lane quad owns one head (D=16).
__global__ void __launch_bounds__(256) aggregate_kernel(float* __restrict__ out)
{
    int warp = (blockIdx.x * blockDim.x + threadIdx.x) >> 5;
    int lane = threadIdx.x & 31;
    if (warp >= N_NODES) return;
    const int node = warp;

    const float4 q = *reinterpret_cast<const float4*>(&g_Q[node * 128 + lane * 4]);
    float4 acc0 = make_float4(0.f, 0.f, 0.f, 0.f);
    float4 acc1 = make_float4(0.f, 0.f, 0.f, 0.f);
    float  zz0 = 0.f, zz1 = 0.f;

    const int beg = g_row_off[node];
    const int end = g_row_off[node + 1];
    int i = beg;

    for (; i + 2 <= end; i += 2) {
        int s0 = g_esrc[i];
        int s1 = g_esrc[i + 1];
        uint4 kv0 = *reinterpret_cast<const uint4*>(&g_KV[s0 * 128 + lane * 4]);
        uint4 kv1 = *reinterpret_cast<const uint4*>(&g_KV[s1 * 128 + lane * 4]);

        float2 k0a = __half22float2(*reinterpret_cast<__half2*>(&kv0.x));
        float2 k0b = __half22float2(*reinterpret_cast<__half2*>(&kv0.y));
        float2 k1a = __half22float2(*reinterpret_cast<__half2*>(&kv1.x));
        float2 k1b = __half22float2(*reinterpret_cast<__half2*>(&kv1.y));

        float p0 = q.x * k0a.x + q.y * k0a.y + q.z * k0b.x + q.w * k0b.y;
        float p1 = q.x * k1a.x + q.y * k1a.y + q.z * k1b.x + q.w * k1b.y;
        p0 += __shfl_xor_sync(0xffffffffu, p0, 1);
        p1 += __shfl_xor_sync(0xffffffffu, p1, 1);
        p0 += __shfl_xor_sync(0xffffffffu, p0, 2);
        p1 += __shfl_xor_sync(0xffffffffu, p1, 2);

        float w0 = __expf(fminf(fmaxf(p0 * 0.25f, -5.f), 5.f));
        float w1 = __expf(fminf(fmaxf(p1 * 0.25f, -5.f), 5.f));

        float2 v0a = __half22float2(*reinterpret_cast<__half2*>(&kv0.z));
        float2 v0b = __half22float2(*reinterpret_cast<__half2*>(&kv0.w));
        float2 v1a = __half22float2(*reinterpret_cast<__half2*>(&kv1.z));
        float2 v1b = __half22float2(*reinterpret_cast<__half2*>(&kv1.w));

        acc0.x += v0a.x * w0;  acc0.y += v0a.y * w0;
        acc0.z += v0b.x * w0;  acc0.w += v0b.y * w0;
        acc1.x += v1a.x * w1;  acc1.y += v1a.y * w1;
        acc1.z += v1b.x * w1;  acc1.w += v1b.y * w1;
        zz0 += w0;
        zz1 += w1;
    }

    if (i < end) {
        int s = g_esrc[i];
        uint4 kv = *reinterpret_cast<const uint4*>(&g_KV[s * 128 + lane * 4]);
        float2 ka = __half22float2(*reinterpret_cast<__half2*>(&kv.x));
        float2 kb = __half22float2(*reinterpret_cast<__half2*>(&kv.y));
        float p = q.x * ka.x + q.y * ka.y + q.z * kb.x + q.w * kb.y;
        p += __shfl_xor_sync(0xffffffffu, p, 1);
        p += __shfl_xor_sync(0xffffffffu, p, 2);
        float wgt = __expf(fminf(fmaxf(p * 0.25f, -5.f), 5.f));
        float2 va = __half22float2(*reinterpret_cast<__half2*>(&kv.z));
        float2 vb = __half22float2(*reinterpret_cast<__half2*>(&kv.w));
        acc0.x += va.x * wgt;  acc0.y += va.y * wgt;
        acc0.z += vb.x * wgt;  acc0.w += vb.y * wgt;
        zz0 += wgt;
    }

    float inv = 1.f / (zz0 + zz1 + 1e-6f);
    float4 o = make_float4((acc0.x + acc1.x) * inv, (acc0.y + acc1.y) * inv,
                           (acc0.z + acc1.z) * inv, (acc0.w + acc1.w) * inv);
    *reinterpret_cast<float4*>(&out[node * 128 + lane * 4]) = o;

    if (lane == 0) g_cnt[node] = 0;                 // restore invariant for next launch
}

// ---------------- launch ----------------
extern "C" void kernel_launch(void* const* d_in, const int* in_sizes, int n_in,
                              void* d_out, int out_size)
{
    const float* h   = (const float*)d_in[0];
    // d_in[1] (e), d_in[8] (We), d_in[9] (be) are unused by the reference output.
    const int*   src = (const int*)d_in[2];
    const int*   dst = (const int*)d_in[3];
    const float* Wq  = (const float*)d_in[4];
    const float* bq  = (const float*)d_in[5];
    const float* Wk  = (const float*)d_in[6];
    const float* bk  = (const float*)d_in[7];
    const float* Wv  = (const float*)d_in[10];
    const float* bv  = (const float*)d_in[11];
    float* out = (float*)d_out;

    dim3 prep_grid(M_TILES, 1, 3);  // z=0: A-frag split (800k threads), z=1: count, z=2: B frags
    prep_kernel<<<prep_grid, 256>>>(h, dst, Wq, Wk, Wv);

    scan_part_kernel<<<SCAN_BLOCKS, 256>>>();
    scan_final_kernel<<<SCAN_BLOCKS, 256>>>();

    dim3 gs_grid(M_TILES, 1, 2);    // z=0: gemm tiles, z=1: scatter (hidden under gemm)
    gemm_scatter<<<gs_grid, 128>>>(bq, bk, bv, src, dst);

    int agg_blocks = (N_NODES + 7) / 8;   // 8 warps (nodes) per 256-thread block
    aggregate_kernel<<<agg_blocks, 256>>>(out);
}

// round 13
// speedup vs baseline: 2.1133x; 1.2869x over previous
#include <cuda_runtime.h>
#include <cuda_fp16.h>
#include <cstdint>

#define N_NODES 50000
#define N_EDGES 800000
#define SCAN_BLOCKS ((N_NODES + 255) / 256)   // 196
#define M_TILES (N_NODES / 16)                // 3125, exact

// ---------------- scratch (static __device__, zero-initialized at load) ----------------
__device__ float    g_Q[N_NODES * 128];
// interleaved fp16 K/V: per node 128 words; lane l owns words 4l..4l+3 = {K2l,K2l+1,V2l,V2l+1}
__device__ uint32_t g_KV[N_NODES * 128];
__device__ int      g_row_off[N_NODES + 1];
__device__ int      g_cnt[N_NODES];           // counts -> cursors; re-zeroed by aggregate
__device__ int      g_esrc[N_EDGES];          // src node id per CSR slot
__device__ int      g_part[SCAN_BLOCKS];

// fp16 A fragments: [mtile][ks][lane] -> uint4 {a0,a1,a2,a3} (half2 words)
__device__ uint4 g_hf[M_TILES * 8 * 32];
// fp16 B fragments, paired: [z][ks][w][lane][pair] -> uint4 {nt_even.b0,b1, nt_odd.b0,b1}
__device__ uint4 g_wf4[3][8][4][32][2];

__device__ __forceinline__ uint32_t pack_h2(float a, float b) {
    __half2 h = __floats2half2_rn(a, b);
    return *reinterpret_cast<uint32_t*>(&h);
}

// ---------------- prep: z=0 A-fragment fp16 pack of h, z=1 edge count, z=2 B fragments ----------------
// grid (3125, 1, 3) x 256 threads
__global__ void __launch_bounds__(256) prep_kernel(
    const float* __restrict__ h, const int* __restrict__ dst,
    const float* __restrict__ Wq, const float* __restrict__ Wk, const float* __restrict__ Wv)
{
    const int z = blockIdx.z;
    const int tid = blockIdx.x * 256 + threadIdx.x;   // < 800000

    if (z == 0) {
        // tid -> (mtile, ks, lane); emit one uint4 fp16 A-frag
        int lane = tid & 31;
        int ks   = (tid >> 5) & 7;
        int mt   = tid >> 8;                 // < 3125
        int g = lane >> 2, t = lane & 3;
        int r0 = mt * 16 + g;
        int r1 = r0 + 8;
        int base = ks * 16 + 2 * t;
        float2 f0 = *reinterpret_cast<const float2*>(&h[r0 * 128 + base]);       // a0
        float2 f2 = *reinterpret_cast<const float2*>(&h[r0 * 128 + base + 8]);   // a2
        float2 f1 = *reinterpret_cast<const float2*>(&h[r1 * 128 + base]);       // a1
        float2 f3 = *reinterpret_cast<const float2*>(&h[r1 * 128 + base + 8]);   // a3
        uint4 a;
        a.x = pack_h2(f0.x, f0.y);
        a.y = pack_h2(f1.x, f1.y);
        a.z = pack_h2(f2.x, f2.y);
        a.w = pack_h2(f3.x, f3.y);
        g_hf[tid] = a;
    } else if (z == 1) {
        if (tid < N_EDGES) atomicAdd(&g_cnt[dst[tid]], 1);
    } else {
        if (tid >= 3 * 8 * 16 * 32) return;
        int lane = tid & 31;
        int nt   = (tid >> 5) & 15;
        int ks   = (tid >> 9) & 7;
        int zz   = tid >> 12;
        const float* W = (zz == 0) ? Wq : (zz == 1) ? Wk : Wv;
        int g = lane >> 2, t = lane & 3;
        int n  = nt * 8 + g;
        int kb = ks * 16 + t * 2;
        uint2 b;
        b.x = pack_h2(W[(kb + 0) * 128 + n], W[(kb + 1) * 128 + n]);
        b.y = pack_h2(W[(kb + 8) * 128 + n], W[(kb + 9) * 128 + n]);
        int w = nt >> 2, p = (nt >> 1) & 1, which = nt & 1;
        reinterpret_cast<uint2*>(&g_wf4[zz][ks][w][lane][p])[which] = b;
    }
}

// ---------------- tensor-core GEMM (z=0) + CSR scatter (z=1), one launch ----------------
__device__ __forceinline__ void mma_f16(float& c0, float& c1, float& c2, float& c3,
                                        uint32_t a0, uint32_t a1, uint32_t a2, uint32_t a3,
                                        uint32_t b0, uint32_t b1)
{
    asm volatile(
        "mma.sync.aligned.m16n8k16.row.col.f32.f16.f16.f32 "
        "{%0,%1,%2,%3},{%4,%5,%6,%7},{%8,%9},{%0,%1,%2,%3};"
        : "+f"(c0), "+f"(c1), "+f"(c2), "+f"(c3)
        : "r"(a0), "r"(a1), "r"(a2), "r"(a3), "r"(b0), "r"(b1));
}

// z=0: CTA = 16 m-rows x 128 n-cols x 3 weights, single fp16 pass:
//      96 MMAs, 8 A LDG.128 + 48 B LDG.128 per warp. Low live set -> higher occ.
// z=1: scatter — latency-bound, rides in gemm's idle issue/LSU slots.
__global__ void __launch_bounds__(128) gemm_scatter(
    const float* __restrict__ bq, const float* __restrict__ bk, const float* __restrict__ bv,
    const int* __restrict__ src, const int* __restrict__ dst)
{
    if (blockIdx.z == 1) {
        int tid = blockIdx.x * 128 + threadIdx.x;
        #pragma unroll
        for (int r = 0; r < 2; r++) {
            int e = tid + r * (M_TILES * 128);
            int p = atomicAdd(&g_cnt[dst[e]], 1);
            g_esrc[p] = src[e];
        }
        return;
    }

    const int m0   = blockIdx.x * 16;
    const int w    = threadIdx.x >> 5;
    const int lane = threadIdx.x & 31;
    const int g    = lane >> 2;
    const int t    = lane & 3;

    float c[3][4][4];
    #pragma unroll
    for (int z = 0; z < 3; z++) {
        const float* bias = (z == 0) ? bq : (z == 1) ? bk : bv;
        #pragma unroll
        for (int nt = 0; nt < 4; nt++) {
            int col = (w * 4 + nt) * 8 + t * 2;
            float b0 = bias[col], b1 = bias[col + 1];
            c[z][nt][0] = b0; c[z][nt][1] = b1;
            c[z][nt][2] = b0; c[z][nt][3] = b1;
        }
    }

    const int afrag_base = blockIdx.x * 8 * 32 + lane;   // + ks*32

    #pragma unroll
    for (int ks = 0; ks < 8; ks++) {
        uint4 a = g_hf[afrag_base + ks * 32];
        #pragma unroll
        for (int z = 0; z < 3; z++) {
            uint4 bp0 = g_wf4[z][ks][w][lane][0];
            uint4 bp1 = g_wf4[z][ks][w][lane][1];
            mma_f16(c[z][0][0], c[z][0][1], c[z][0][2], c[z][0][3],
                    a.x, a.y, a.z, a.w, bp0.x, bp0.y);
            mma_f16(c[z][1][0], c[z][1][1], c[z][1][2], c[z][1][3],
                    a.x, a.y, a.z, a.w, bp0.z, bp0.w);
            mma_f16(c[z][2][0], c[z][2][1], c[z][2][2], c[z][2][3],
                    a.x, a.y, a.z, a.w, bp1.x, bp1.y);
            mma_f16(c[z][3][0], c[z][3][1], c[z][3][2], c[z][3][3],
                    a.x, a.y, a.z, a.w, bp1.z, bp1.w);
        }
    }

    #pragma unroll
    for (int nt = 0; nt < 4; nt++) {
        int col = (w * 4 + nt) * 8 + t * 2;
        // Q fp32
        *reinterpret_cast<float2*>(&g_Q[(m0 + g) * 128 + col])     = make_float2(c[0][nt][0], c[0][nt][1]);
        *reinterpret_cast<float2*>(&g_Q[(m0 + g + 8) * 128 + col]) = make_float2(c[0][nt][2], c[0][nt][3]);
        // K, V fp16 interleaved: word index j = col/2 -> slot (j>>1)*4 + (j&1) (+2 for V)
        uint32_t klo = pack_h2(c[1][nt][0], c[1][nt][1]);
        uint32_t khi = pack_h2(c[1][nt][2], c[1][nt][3]);
        uint32_t vlo = pack_h2(c[2][nt][0], c[2][nt][1]);
        uint32_t vhi = pack_h2(c[2][nt][2], c[2][nt][3]);
        int j = col / 2;
        int slot = (j >> 1) * 4 + (j & 1);
        g_KV[(m0 + g) * 128 + slot]         = klo;
        g_KV[(m0 + g + 8) * 128 + slot]     = khi;
        g_KV[(m0 + g) * 128 + slot + 2]     = vlo;
        g_KV[(m0 + g + 8) * 128 + slot + 2] = vhi;
    }
}

// ---------------- parallel scan, stage 1 ----------------
__global__ void __launch_bounds__(256) scan_part_kernel()
{
    __shared__ int ws[8];
    int gid = blockIdx.x * 256 + threadIdx.x;
    int v = (gid < N_NODES) ? g_cnt[gid] : 0;
    int s = __reduce_add_sync(0xffffffffu, v);
    if ((threadIdx.x & 31) == 0) ws[threadIdx.x >> 5] = s;
    __syncthreads();
    if (threadIdx.x == 0) {
        int tot = 0;
        #pragma unroll
        for (int j = 0; j < 8; j++) tot += ws[j];
        g_part[blockIdx.x] = tot;
    }
}

// ---------------- parallel scan, stage 2 ----------------
__global__ void __launch_bounds__(256) scan_final_kernel()
{
    __shared__ int ps[8];
    __shared__ int ws[8];
    const int t = threadIdx.x, b = blockIdx.x;
    const int lane = t & 31, w = t >> 5;

    int pv = (t < b) ? g_part[t] : 0;
    int psum = __reduce_add_sync(0xffffffffu, pv);
    if (lane == 0) ps[w] = psum;
    __syncthreads();
    int offset = 0;
    #pragma unroll
    for (int j = 0; j < 8; j++) offset += ps[j];

    int gid = b * 256 + t;
    int c = (gid < N_NODES) ? g_cnt[gid] : 0;
    int incl = c;
    #pragma unroll
    for (int d = 1; d < 32; d <<= 1) {
        int u = __shfl_up_sync(0xffffffffu, incl, d);
        if (lane >= d) incl += u;
    }
    if (lane == 31) ws[w] = incl;
    __syncthreads();
    int woff = 0;
    #pragma unroll
    for (int j = 0; j < 8; j++) woff += (j < w) ? ws[j] : 0;

    int excl = offset + woff + incl - c;
    if (gid < N_NODES) {
        g_row_off[gid] = excl;
        g_cnt[gid]     = excl;           // cursor for scatter
    }
    if (gid == N_NODES - 1)
        g_row_off[N_NODES] = excl + c;
}

// ---------------- aggregation: one warp per dst node, 2-edge software pipeline ----------------
// lane l owns columns 4l..4l+3; each 4-lane quad owns one head (D=16).
__global__ void __launch_bounds__(256) aggregate_kernel(float* __restrict__ out)
{
    int warp = (blockIdx.x * blockDim.x + threadIdx.x) >> 5;
    int lane = threadIdx.x & 31;
    if (warp >= N_NODES) return;
    const int node = warp;

    const float4 q = *reinterpret_cast<const float4*>(&g_Q[node * 128 + lane * 4]);
    float4 acc0 = make_float4(0.f, 0.f, 0.f, 0.f);
    float4 acc1 = make_float4(0.f, 0.f, 0.f, 0.f);
    float  zz0 = 0.f, zz1 = 0.f;

    const int beg = g_row_off[node];
    const int end = g_row_off[node + 1];
    int i = beg;

    for (; i + 2 <= end; i += 2) {
        int s0 = g_esrc[i];
        int s1 = g_esrc[i + 1];
        uint4 kv0 = *reinterpret_cast<const uint4*>(&g_KV[s0 * 128 + lane * 4]);
        uint4 kv1 = *reinterpret_cast<const uint4*>(&g_KV[s1 * 128 + lane * 4]);

        float2 k0a = __half22float2(*reinterpret_cast<__half2*>(&kv0.x));
        float2 k0b = __half22float2(*reinterpret_cast<__half2*>(&kv0.y));
        float2 k1a = __half22float2(*reinterpret_cast<__half2*>(&kv1.x));
        float2 k1b = __half22float2(*reinterpret_cast<__half2*>(&kv1.y));

        float p0 = q.x * k0a.x + q.y * k0a.y + q.z * k0b.x + q.w * k0b.y;
        float p1 = q.x * k1a.x + q.y * k1a.y + q.z * k1b.x + q.w * k1b.y;
        p0 += __shfl_xor_sync(0xffffffffu, p0, 1);
        p1 += __shfl_xor_sync(0xffffffffu, p1, 1);
        p0 += __shfl_xor_sync(0xffffffffu, p0, 2);
        p1 += __shfl_xor_sync(0xffffffffu, p1, 2);

        float w0 = __expf(fminf(fmaxf(p0 * 0.25f, -5.f), 5.f));
        float w1 = __expf(fminf(fmaxf(p1 * 0.25f, -5.f), 5.f));

        float2 v0a = __half22float2(*reinterpret_cast<__half2*>(&kv0.z));
        float2 v0b = __half22float2(*reinterpret_cast<__half2*>(&kv0.w));
        float2 v1a = __half22float2(*reinterpret_cast<__half2*>(&kv1.z));
        float2 v1b = __half22float2(*reinterpret_cast<__half2*>(&kv1.w));

        acc0.x += v0a.x * w0;  acc0.y += v0a.y * w0;
        acc0.z += v0b.x * w0;  acc0.w += v0b.y * w0;
        acc1.x += v1a.x * w1;  acc1.y += v1a.y * w1;
        acc1.z += v1b.x * w1;  acc1.w += v1b.y * w1;
        zz0 += w0;
        zz1 += w1;
    }

    if (i < end) {
        int s = g_esrc[i];
        uint4 kv = *reinterpret_cast<const uint4*>(&g_KV[s * 128 + lane * 4]);
        float2 ka = __half22float2(*reinterpret_cast<__half2*>(&kv.x));
        float2 kb = __half22float2(*reinterpret_cast<__half2*>(&kv.y));
        float p = q.x * ka.x + q.y * ka.y + q.z * kb.x + q.w * kb.y;
        p += __shfl_xor_sync(0xffffffffu, p, 1);
        p += __shfl_xor_sync(0xffffffffu, p, 2);
        float wgt = __expf(fminf(fmaxf(p * 0.25f, -5.f), 5.f));
        float2 va = __half22float2(*reinterpret_cast<__half2*>(&kv.z));
        float2 vb = __half22float2(*reinterpret_cast<__half2*>(&kv.w));
        acc0.x += va.x * wgt;  acc0.y += va.y * wgt;
        acc0.z += vb.x * wgt;  acc0.w += vb.y * wgt;
        zz0 += wgt;
    }

    float inv = 1.f / (zz0 + zz1 + 1e-6f);
    float4 o = make_float4((acc0.x + acc1.x) * inv, (acc0.y + acc1.y) * inv,
                           (acc0.z + acc1.z) * inv, (acc0.w + acc1.w) * inv);
    *reinterpret_cast<float4*>(&out[node * 128 + lane * 4]) = o;

    if (lane == 0) g_cnt[node] = 0;                 // restore invariant for next launch
}

// ---------------- launch ----------------
extern "C" void kernel_launch(void* const* d_in, const int* in_sizes, int n_in,
                              void* d_out, int out_size)
{
    const float* h   = (const float*)d_in[0];
    // d_in[1] (e), d_in[8] (We), d_in[9] (be) are unused by the reference output.
    const int*   src = (const int*)d_in[2];
    const int*   dst = (const int*)d_in[3];
    const float* Wq  = (const float*)d_in[4];
    const float* bq  = (const float*)d_in[5];
    const float* Wk  = (const float*)d_in[6];
    const float* bk  = (const float*)d_in[7];
    const float* Wv  = (const float*)d_in[10];
    const float* bv  = (const float*)d_in[11];
    float* out = (float*)d_out;

    dim3 prep_grid(M_TILES, 1, 3);  // z=0: A-frag pack (800k threads), z=1: count, z=2: B frags
    prep_kernel<<<prep_grid, 256>>>(h, dst, Wq, Wk, Wv);

    scan_part_kernel<<<SCAN_BLOCKS, 256>>>();
    scan_final_kernel<<<SCAN_BLOCKS, 256>>>();

    dim3 gs_grid(M_TILES, 1, 2);    // z=0: gemm tiles, z=1: scatter (hidden under gemm)
    gemm_scatter<<<gs_grid, 128>>>(bq, bk, bv, src, dst);

    int agg_blocks = (N_NODES + 7) / 8;   // 8 warps (nodes) per 256-thread block
    aggregate_kernel<<<agg_blocks, 256>>>(out);
}

// round 14
// speedup vs baseline: 2.2504x; 1.0649x over previous
#include <cuda_runtime.h>
#include <cuda_fp16.h>
#include <cstdint>

#define N_NODES 50000
#define N_EDGES 800000
#define SCAN_BLOCKS ((N_NODES + 255) / 256)   // 196
#define M_TILES (N_NODES / 16)                // 3125, exact

// ---------------- scratch (static __device__, zero-initialized at load) ----------------
__device__ float    g_Q[N_NODES * 128];
// interleaved fp16 K/V: per node 128 words; lane l owns words 4l..4l+3 = {K2l,K2l+1,V2l,V2l+1}
__device__ uint32_t g_KV[N_NODES * 128];
__device__ int      g_row_off[N_NODES + 1];
__device__ int      g_cnt[N_NODES];           // counts -> cursors; re-zeroed by aggregate
__device__ int      g_esrc[N_EDGES];          // src node id per CSR slot
__device__ int      g_part[SCAN_BLOCKS];

// fp16 A fragments: [mtile][ks][lane] -> uint4 {a0,a1,a2,a3} (half2 words); lane-contiguous
__device__ uint4 g_hf[M_TILES * 8 * 32];
// fp16 B fragments: [z][ks][w][pair][lane] -> uint4 {nt_even.b0,b1, nt_odd.b0,b1}
// pair OUTSIDE lane => every warp load is lane-contiguous (4 L1 lines, not 16)
__device__ uint4 g_wf4[3][8][4][2][32];

__device__ __forceinline__ uint32_t pack_h2(float a, float b) {
    __half2 h = __floats2half2_rn(a, b);
    return *reinterpret_cast<uint32_t*>(&h);
}

// ---------------- prep: z=0 A-fragment fp16 pack of h, z=1 edge count, z=2 B fragments ----------------
// grid (3125, 1, 3) x 256 threads
__global__ void __launch_bounds__(256) prep_kernel(
    const float* __restrict__ h, const int* __restrict__ dst,
    const float* __restrict__ Wq, const float* __restrict__ Wk, const float* __restrict__ Wv)
{
    const int z = blockIdx.z;
    const int tid = blockIdx.x * 256 + threadIdx.x;   // < 800000

    if (z == 0) {
        // tid -> (mtile, ks, lane); emit one uint4 fp16 A-frag
        int lane = tid & 31;
        int ks   = (tid >> 5) & 7;
        int mt   = tid >> 8;                 // < 3125
        int g = lane >> 2, t = lane & 3;
        int r0 = mt * 16 + g;
        int r1 = r0 + 8;
        int base = ks * 16 + 2 * t;
        float2 f0 = *reinterpret_cast<const float2*>(&h[r0 * 128 + base]);       // a0
        float2 f2 = *reinterpret_cast<const float2*>(&h[r0 * 128 + base + 8]);   // a2
        float2 f1 = *reinterpret_cast<const float2*>(&h[r1 * 128 + base]);       // a1
        float2 f3 = *reinterpret_cast<const float2*>(&h[r1 * 128 + base + 8]);   // a3
        uint4 a;
        a.x = pack_h2(f0.x, f0.y);
        a.y = pack_h2(f1.x, f1.y);
        a.z = pack_h2(f2.x, f2.y);
        a.w = pack_h2(f3.x, f3.y);
        g_hf[tid] = a;
    } else if (z == 1) {
        if (tid < N_EDGES) atomicAdd(&g_cnt[dst[tid]], 1);
    } else {
        if (tid >= 3 * 8 * 16 * 32) return;
        int lane = tid & 31;
        int nt   = (tid >> 5) & 15;
        int ks   = (tid >> 9) & 7;
        int zz   = tid >> 12;
        const float* W = (zz == 0) ? Wq : (zz == 1) ? Wk : Wv;
        int g = lane >> 2, t = lane & 3;
        int n  = nt * 8 + g;
        int kb = ks * 16 + t * 2;
        uint2 b;
        b.x = pack_h2(W[(kb + 0) * 128 + n], W[(kb + 1) * 128 + n]);
        b.y = pack_h2(W[(kb + 8) * 128 + n], W[(kb + 9) * 128 + n]);
        int w = nt >> 2, p = (nt >> 1) & 1, which = nt & 1;
        reinterpret_cast<uint2*>(&g_wf4[zz][ks][w][p][lane])[which] = b;
    }
}

// ---------------- tensor-core GEMM (z=0) + CSR scatter (z=1), one launch ----------------
__device__ __forceinline__ void mma_f16(float& c0, float& c1, float& c2, float& c3,
                                        uint32_t a0, uint32_t a1, uint32_t a2, uint32_t a3,
                                        uint32_t b0, uint32_t b1)
{
    asm volatile(
        "mma.sync.aligned.m16n8k16.row.col.f32.f16.f16.f32 "
        "{%0,%1,%2,%3},{%4,%5,%6,%7},{%8,%9},{%0,%1,%2,%3};"
        : "+f"(c0), "+f"(c1), "+f"(c2), "+f"(c3)
        : "r"(a0), "r"(a1), "r"(a2), "r"(a3), "r"(b0), "r"(b1));
}

// z=0: CTA = 16 m-rows x 128 n-cols x 3 weights, single fp16 pass, all loads coalesced LDG.128.
// z=1: scatter — latency-bound, rides in gemm's idle issue/LSU slots.
__global__ void __launch_bounds__(128) gemm_scatter(
    const float* __restrict__ bq, const float* __restrict__ bk, const float* __restrict__ bv,
    const int* __restrict__ src, const int* __restrict__ dst)
{
    if (blockIdx.z == 1) {
        int tid = blockIdx.x * 128 + threadIdx.x;
        #pragma unroll
        for (int r = 0; r < 2; r++) {
            int e = tid + r * (M_TILES * 128);
            int p = atomicAdd(&g_cnt[dst[e]], 1);
            g_esrc[p] = src[e];
        }
        return;
    }

    const int m0   = blockIdx.x * 16;
    const int w    = threadIdx.x >> 5;
    const int lane = threadIdx.x & 31;
    const int g    = lane >> 2;
    const int t    = lane & 3;

    float c[3][4][4];
    #pragma unroll
    for (int z = 0; z < 3; z++) {
        const float* bias = (z == 0) ? bq : (z == 1) ? bk : bv;
        #pragma unroll
        for (int nt = 0; nt < 4; nt++) {
            int col = (w * 4 + nt) * 8 + t * 2;
            float b0 = bias[col], b1 = bias[col + 1];
            c[z][nt][0] = b0; c[z][nt][1] = b1;
            c[z][nt][2] = b0; c[z][nt][3] = b1;
        }
    }

    const int afrag_base = blockIdx.x * 8 * 32 + lane;   // + ks*32

    #pragma unroll
    for (int ks = 0; ks < 8; ks++) {
        uint4 a = g_hf[afrag_base + ks * 32];
        #pragma unroll
        for (int z = 0; z < 3; z++) {
            uint4 bp0 = g_wf4[z][ks][w][0][lane];
            uint4 bp1 = g_wf4[z][ks][w][1][lane];
            mma_f16(c[z][0][0], c[z][0][1], c[z][0][2], c[z][0][3],
                    a.x, a.y, a.z, a.w, bp0.x, bp0.y);
            mma_f16(c[z][1][0], c[z][1][1], c[z][1][2], c[z][1][3],
                    a.x, a.y, a.z, a.w, bp0.z, bp0.w);
            mma_f16(c[z][2][0], c[z][2][1], c[z][2][2], c[z][2][3],
                    a.x, a.y, a.z, a.w, bp1.x, bp1.y);
            mma_f16(c[z][3][0], c[z][3][1], c[z][3][2], c[z][3][3],
                    a.x, a.y, a.z, a.w, bp1.z, bp1.w);
        }
    }

    #pragma unroll
    for (int nt = 0; nt < 4; nt++) {
        int col = (w * 4 + nt) * 8 + t * 2;
        // Q fp32
        *reinterpret_cast<float2*>(&g_Q[(m0 + g) * 128 + col])     = make_float2(c[0][nt][0], c[0][nt][1]);
        *reinterpret_cast<float2*>(&g_Q[(m0 + g + 8) * 128 + col]) = make_float2(c[0][nt][2], c[0][nt][3]);
        // K, V fp16 interleaved: word index j = col/2 -> slot (j>>1)*4 + (j&1) (+2 for V)
        uint32_t klo = pack_h2(c[1][nt][0], c[1][nt][1]);
        uint32_t khi = pack_h2(c[1][nt][2], c[1][nt][3]);
        uint32_t vlo = pack_h2(c[2][nt][0], c[2][nt][1]);
        uint32_t vhi = pack_h2(c[2][nt][2], c[2][nt][3]);
        int j = col / 2;
        int slot = (j >> 1) * 4 + (j & 1);
        g_KV[(m0 + g) * 128 + slot]         = klo;
        g_KV[(m0 + g + 8) * 128 + slot]     = khi;
        g_KV[(m0 + g) * 128 + slot + 2]     = vlo;
        g_KV[(m0 + g + 8) * 128 + slot + 2] = vhi;
    }
}

// ---------------- parallel scan, stage 1 ----------------
__global__ void __launch_bounds__(256) scan_part_kernel()
{
    __shared__ int ws[8];
    int gid = blockIdx.x * 256 + threadIdx.x;
    int v = (gid < N_NODES) ? g_cnt[gid] : 0;
    int s = __reduce_add_sync(0xffffffffu, v);
    if ((threadIdx.x & 31) == 0) ws[threadIdx.x >> 5] = s;
    __syncthreads();
    if (threadIdx.x == 0) {
        int tot = 0;
        #pragma unroll
        for (int j = 0; j < 8; j++) tot += ws[j];
        g_part[blockIdx.x] = tot;
    }
}

// ---------------- parallel scan, stage 2 ----------------
__global__ void __launch_bounds__(256) scan_final_kernel()
{
    __shared__ int ps[8];
    __shared__ int ws[8];
    const int t = threadIdx.x, b = blockIdx.x;
    const int lane = t & 31, w = t >> 5;

    int pv = (t < b) ? g_part[t] : 0;
    int psum = __reduce_add_sync(0xffffffffu, pv);
    if (lane == 0) ps[w] = psum;
    __syncthreads();
    int offset = 0;
    #pragma unroll
    for (int j = 0; j < 8; j++) offset += ps[j];

    int gid = b * 256 + t;
    int c = (gid < N_NODES) ? g_cnt[gid] : 0;
    int incl = c;
    #pragma unroll
    for (int d = 1; d < 32; d <<= 1) {
        int u = __shfl_up_sync(0xffffffffu, incl, d);
        if (lane >= d) incl += u;
    }
    if (lane == 31) ws[w] = incl;
    __syncthreads();
    int woff = 0;
    #pragma unroll
    for (int j = 0; j < 8; j++) woff += (j < w) ? ws[j] : 0;

    int excl = offset + woff + incl - c;
    if (gid < N_NODES) {
        g_row_off[gid] = excl;
        g_cnt[gid]     = excl;           // cursor for scatter
    }
    if (gid == N_NODES - 1)
        g_row_off[N_NODES] = excl + c;
}

// ---------------- aggregation: one warp per dst node, 2-edge software pipeline ----------------
// lane l owns columns 4l..4l+3; each 4-lane quad owns one head (D=16).
__global__ void __launch_bounds__(256) aggregate_kernel(float* __restrict__ out)
{
    int warp = (blockIdx.x * blockDim.x + threadIdx.x) >> 5;
    int lane = threadIdx.x & 31;
    if (warp >= N_NODES) return;
    const int node = warp;

    const float4 q = *reinterpret_cast<const float4*>(&g_Q[node * 128 + lane * 4]);
    float4 acc0 = make_float4(0.f, 0.f, 0.f, 0.f);
    float4 acc1 = make_float4(0.f, 0.f, 0.f, 0.f);
    float  zz0 = 0.f, zz1 = 0.f;

    const int beg = g_row_off[node];
    const int end = g_row_off[node + 1];
    int i = beg;

    for (; i + 2 <= end; i += 2) {
        int s0 = g_esrc[i];
        int s1 = g_esrc[i + 1];
        uint4 kv0 = *reinterpret_cast<const uint4*>(&g_KV[s0 * 128 + lane * 4]);
        uint4 kv1 = *reinterpret_cast<const uint4*>(&g_KV[s1 * 128 + lane * 4]);

        float2 k0a = __half22float2(*reinterpret_cast<__half2*>(&kv0.x));
        float2 k0b = __half22float2(*reinterpret_cast<__half2*>(&kv0.y));
        float2 k1a = __half22float2(*reinterpret_cast<__half2*>(&kv1.x));
        float2 k1b = __half22float2(*reinterpret_cast<__half2*>(&kv1.y));

        float p0 = q.x * k0a.x + q.y * k0a.y + q.z * k0b.x + q.w * k0b.y;
        float p1 = q.x * k1a.x + q.y * k1a.y + q.z * k1b.x + q.w * k1b.y;
        p0 += __shfl_xor_sync(0xffffffffu, p0, 1);
        p1 += __shfl_xor_sync(0xffffffffu, p1, 1);
        p0 += __shfl_xor_sync(0xffffffffu, p0, 2);
        p1 += __shfl_xor_sync(0xffffffffu, p1, 2);

        float w0 = __expf(fminf(fmaxf(p0 * 0.25f, -5.f), 5.f));
        float w1 = __expf(fminf(fmaxf(p1 * 0.25f, -5.f), 5.f));

        float2 v0a = __half22float2(*reinterpret_cast<__half2*>(&kv0.z));
        float2 v0b = __half22float2(*reinterpret_cast<__half2*>(&kv0.w));
        float2 v1a = __half22float2(*reinterpret_cast<__half2*>(&kv1.z));
        float2 v1b = __half22float2(*reinterpret_cast<__half2*>(&kv1.w));

        acc0.x += v0a.x * w0;  acc0.y += v0a.y * w0;
        acc0.z += v0b.x * w0;  acc0.w += v0b.y * w0;
        acc1.x += v1a.x * w1;  acc1.y += v1a.y * w1;
        acc1.z += v1b.x * w1;  acc1.w += v1b.y * w1;
        zz0 += w0;
        zz1 += w1;
    }

    if (i < end) {
        int s = g_esrc[i];
        uint4 kv = *reinterpret_cast<const uint4*>(&g_KV[s * 128 + lane * 4]);
        float2 ka = __half22float2(*reinterpret_cast<__half2*>(&kv.x));
        float2 kb = __half22float2(*reinterpret_cast<__half2*>(&kv.y));
        float p = q.x * ka.x + q.y * ka.y + q.z * kb.x + q.w * kb.y;
        p += __shfl_xor_sync(0xffffffffu, p, 1);
        p += __shfl_xor_sync(0xffffffffu, p, 2);
        float wgt = __expf(fminf(fmaxf(p * 0.25f, -5.f), 5.f));
        float2 va = __half22float2(*reinterpret_cast<__half2*>(&kv.z));
        float2 vb = __half22float2(*reinterpret_cast<__half2*>(&kv.w));
        acc0.x += va.x * wgt;  acc0.y += va.y * wgt;
        acc0.z += vb.x * wgt;  acc0.w += vb.y * wgt;
        zz0 += wgt;
    }

    float inv = 1.f / (zz0 + zz1 + 1e-6f);
    float4 o = make_float4((acc0.x + acc1.x) * inv, (acc0.y + acc1.y) * inv,
                           (acc0.z + acc1.z) * inv, (acc0.w + acc1.w) * inv);
    *reinterpret_cast<float4*>(&out[node * 128 + lane * 4]) = o;

    if (lane == 0) g_cnt[node] = 0;                 // restore invariant for next launch
}

// ---------------- launch ----------------
extern "C" void kernel_launch(void* const* d_in, const int* in_sizes, int n_in,
                              void* d_out, int out_size)
{
    const float* h   = (const float*)d_in[0];
    // d_in[1] (e), d_in[8] (We), d_in[9] (be) are unused by the reference output.
    const int*   src = (const int*)d_in[2];
    const int*   dst = (const int*)d_in[3];
    const float* Wq  = (const float*)d_in[4];
    const float* bq  = (const float*)d_in[5];
    const float* Wk  = (const float*)d_in[6];
    const float* bk  = (const float*)d_in[7];
    const float* Wv  = (const float*)d_in[10];
    const float* bv  = (const float*)d_in[11];
    float* out = (float*)d_out;

    dim3 prep_grid(M_TILES, 1, 3);  // z=0: A-frag pack (800k threads), z=1: count, z=2: B frags
    prep_kernel<<<prep_grid, 256>>>(h, dst, Wq, Wk, Wv);

    scan_part_kernel<<<SCAN_BLOCKS, 256>>>();
    scan_final_kernel<<<SCAN_BLOCKS, 256>>>();

    dim3 gs_grid(M_TILES, 1, 2);    // z=0: gemm tiles, z=1: scatter (hidden under gemm)
    gemm_scatter<<<gs_grid, 128>>>(bq, bk, bv, src, dst);

    int agg_blocks = (N_NODES + 7) / 8;   // 8 warps (nodes) per 256-thread block
    aggregate_kernel<<<agg_blocks, 256>>>(out);
}

// round 15
// speedup vs baseline: 2.2938x; 1.0193x over previous
#include <cuda_runtime.h>
#include <cuda_fp16.h>
#include <cstdint>

#define N_NODES 50000
#define N_EDGES 800000
#define SCAN_BLOCKS ((N_NODES + 255) / 256)   // 196
#define M_TILES (N_NODES / 16)                // 3125, exact
#define G_BLOCKS ((M_TILES + 1) / 2)          // 1563 CTAs, 2 m-tiles each

// ---------------- scratch (static __device__, zero-initialized at load) ----------------
__device__ float    g_Q[N_NODES * 128];
// interleaved fp16 K/V: per node 128 words; lane l owns words 4l..4l+3 = {K2l,K2l+1,V2l,V2l+1}
__device__ uint32_t g_KV[N_NODES * 128];
__device__ int      g_row_off[N_NODES + 1];
__device__ int      g_cnt[N_NODES];           // counts -> cursors; re-zeroed by aggregate
__device__ int      g_esrc[N_EDGES];          // src node id per CSR slot
__device__ int      g_part[SCAN_BLOCKS];

// fp16 A fragments: [mtile][ks][lane] -> uint4 {a0,a1,a2,a3} (half2 words); lane-contiguous
__device__ uint4 g_hf[M_TILES * 8 * 32];
// fp16 B fragments: [z][ks][w][pair][lane]; pair outside lane => lane-contiguous LDG.128
__device__ uint4 g_wf4[3][8][4][2][32];

__device__ __forceinline__ uint32_t pack_h2(float a, float b) {
    __half2 h = __floats2half2_rn(a, b);
    return *reinterpret_cast<uint32_t*>(&h);
}

// ---------------- prep: z=0 A-fragment fp16 pack of h, z=1 edge count, z=2 B fragments ----------------
// grid (3125, 1, 3) x 256 threads
__global__ void __launch_bounds__(256) prep_kernel(
    const float* __restrict__ h, const int* __restrict__ dst,
    const float* __restrict__ Wq, const float* __restrict__ Wk, const float* __restrict__ Wv)
{
    const int z = blockIdx.z;
    const int tid = blockIdx.x * 256 + threadIdx.x;   // < 800000

    if (z == 0) {
        // tid -> (mtile, ks, lane); emit one uint4 fp16 A-frag
        int lane = tid & 31;
        int ks   = (tid >> 5) & 7;
        int mt   = tid >> 8;                 // < 3125
        int g = lane >> 2, t = lane & 3;
        int r0 = mt * 16 + g;
        int r1 = r0 + 8;
        int base = ks * 16 + 2 * t;
        float2 f0 = *reinterpret_cast<const float2*>(&h[r0 * 128 + base]);       // a0
        float2 f2 = *reinterpret_cast<const float2*>(&h[r0 * 128 + base + 8]);   // a2
        float2 f1 = *reinterpret_cast<const float2*>(&h[r1 * 128 + base]);       // a1
        float2 f3 = *reinterpret_cast<const float2*>(&h[r1 * 128 + base + 8]);   // a3
        uint4 a;
        a.x = pack_h2(f0.x, f0.y);
        a.y = pack_h2(f1.x, f1.y);
        a.z = pack_h2(f2.x, f2.y);
        a.w = pack_h2(f3.x, f3.y);
        g_hf[tid] = a;
    } else if (z == 1) {
        if (tid < N_EDGES) atomicAdd(&g_cnt[dst[tid]], 1);
    } else {
        if (tid >= 3 * 8 * 16 * 32) return;
        int lane = tid & 31;
        int nt   = (tid >> 5) & 15;
        int ks   = (tid >> 9) & 7;
        int zz   = tid >> 12;
        const float* W = (zz == 0) ? Wq : (zz == 1) ? Wk : Wv;
        int g = lane >> 2, t = lane & 3;
        int n  = nt * 8 + g;
        int kb = ks * 16 + t * 2;
        uint2 b;
        b.x = pack_h2(W[(kb + 0) * 128 + n], W[(kb + 1) * 128 + n]);
        b.y = pack_h2(W[(kb + 8) * 128 + n], W[(kb + 9) * 128 + n]);
        int w = nt >> 2, p = (nt >> 1) & 1, which = nt & 1;
        reinterpret_cast<uint2*>(&g_wf4[zz][ks][w][p][lane])[which] = b;
    }
}

// ---------------- tensor-core GEMM (z=0) + CSR scatter (z=1), one launch ----------------
__device__ __forceinline__ void mma_f16(float& c0, float& c1, float& c2, float& c3,
                                        uint32_t a0, uint32_t a1, uint32_t a2, uint32_t a3,
                                        uint32_t b0, uint32_t b1)
{
    asm volatile(
        "mma.sync.aligned.m16n8k16.row.col.f32.f16.f16.f32 "
        "{%0,%1,%2,%3},{%4,%5,%6,%7},{%8,%9},{%0,%1,%2,%3};"
        : "+f"(c0), "+f"(c1), "+f"(c2), "+f"(c3)
        : "r"(a0), "r"(a1), "r"(a2), "r"(a3), "r"(b0), "r"(b1));
}

// z=0: CTA = 32 m-rows (2 m-tiles) x 128 n-cols x 3 weights. Each warp runs both m-tiles,
//      reusing B fragment registers: loads/MMA = 64/192 (was 56/96); B L2 traffic halved.
// z=1: scatter — 4 edges/thread, rides in gemm's idle issue/LSU slots.
__global__ void __launch_bounds__(128, 3) gemm_scatter(
    const float* __restrict__ bq, const float* __restrict__ bk, const float* __restrict__ bv,
    const int* __restrict__ src, const int* __restrict__ dst)
{
    if (blockIdx.z == 1) {
        int tid = blockIdx.x * 128 + threadIdx.x;    // < 200064
        #pragma unroll
        for (int r = 0; r < 4; r++) {
            int e = tid + r * (G_BLOCKS * 128);
            if (e < N_EDGES) {
                int p = atomicAdd(&g_cnt[dst[e]], 1);
                g_esrc[p] = src[e];
            }
        }
        return;
    }

    const int mt0  = blockIdx.x * 2;
    const int mt1  = mt0 + 1;
    const bool has2 = (mt1 < M_TILES);
    const int mt1c = has2 ? mt1 : mt0;       // clamp: duplicate compute, guarded store

    const int w    = threadIdx.x >> 5;
    const int lane = threadIdx.x & 31;
    const int g    = lane >> 2;
    const int t    = lane & 3;

    float c0[3][4][4], c1[3][4][4];
    #pragma unroll
    for (int z = 0; z < 3; z++) {
        const float* bias = (z == 0) ? bq : (z == 1) ? bk : bv;
        #pragma unroll
        for (int nt = 0; nt < 4; nt++) {
            int col = (w * 4 + nt) * 8 + t * 2;
            float b0 = bias[col], b1 = bias[col + 1];
            c0[z][nt][0] = b0; c0[z][nt][1] = b1; c0[z][nt][2] = b0; c0[z][nt][3] = b1;
            c1[z][nt][0] = b0; c1[z][nt][1] = b1; c1[z][nt][2] = b0; c1[z][nt][3] = b1;
        }
    }

    const int a0_base = mt0  * 8 * 32 + lane;   // + ks*32
    const int a1_base = mt1c * 8 * 32 + lane;

    #pragma unroll
    for (int ks = 0; ks < 8; ks++) {
        uint4 aA = g_hf[a0_base + ks * 32];
        uint4 aB = g_hf[a1_base + ks * 32];
        #pragma unroll
        for (int z = 0; z < 3; z++) {
            uint4 bp0 = g_wf4[z][ks][w][0][lane];
            uint4 bp1 = g_wf4[z][ks][w][1][lane];
            mma_f16(c0[z][0][0], c0[z][0][1], c0[z][0][2], c0[z][0][3],
                    aA.x, aA.y, aA.z, aA.w, bp0.x, bp0.y);
            mma_f16(c0[z][1][0], c0[z][1][1], c0[z][1][2], c0[z][1][3],
                    aA.x, aA.y, aA.z, aA.w, bp0.z, bp0.w);
            mma_f16(c0[z][2][0], c0[z][2][1], c0[z][2][2], c0[z][2][3],
                    aA.x, aA.y, aA.z, aA.w, bp1.x, bp1.y);
            mma_f16(c0[z][3][0], c0[z][3][1], c0[z][3][2], c0[z][3][3],
                    aA.x, aA.y, aA.z, aA.w, bp1.z, bp1.w);
            mma_f16(c1[z][0][0], c1[z][0][1], c1[z][0][2], c1[z][0][3],
                    aB.x, aB.y, aB.z, aB.w, bp0.x, bp0.y);
            mma_f16(c1[z][1][0], c1[z][1][1], c1[z][1][2], c1[z][1][3],
                    aB.x, aB.y, aB.z, aB.w, bp0.z, bp0.w);
            mma_f16(c1[z][2][0], c1[z][2][1], c1[z][2][2], c1[z][2][3],
                    aB.x, aB.y, aB.z, aB.w, bp1.x, bp1.y);
            mma_f16(c1[z][3][0], c1[z][3][1], c1[z][3][2], c1[z][3][3],
                    aB.x, aB.y, aB.z, aB.w, bp1.z, bp1.w);
        }
    }

    // ---- epilogue m-tile 0 ----
    {
        int m0 = mt0 * 16;
        #pragma unroll
        for (int nt = 0; nt < 4; nt++) {
            int col = (w * 4 + nt) * 8 + t * 2;
            *reinterpret_cast<float2*>(&g_Q[(m0 + g) * 128 + col])     = make_float2(c0[0][nt][0], c0[0][nt][1]);
            *reinterpret_cast<float2*>(&g_Q[(m0 + g + 8) * 128 + col]) = make_float2(c0[0][nt][2], c0[0][nt][3]);
            uint32_t klo = pack_h2(c0[1][nt][0], c0[1][nt][1]);
            uint32_t khi = pack_h2(c0[1][nt][2], c0[1][nt][3]);
            uint32_t vlo = pack_h2(c0[2][nt][0], c0[2][nt][1]);
            uint32_t vhi = pack_h2(c0[2][nt][2], c0[2][nt][3]);
            int j = col / 2;
            int slot = (j >> 1) * 4 + (j & 1);
            g_KV[(m0 + g) * 128 + slot]         = klo;
            g_KV[(m0 + g + 8) * 128 + slot]     = khi;
            g_KV[(m0 + g) * 128 + slot + 2]     = vlo;
            g_KV[(m0 + g + 8) * 128 + slot + 2] = vhi;
        }
    }
    // ---- epilogue m-tile 1 (guarded) ----
    if (has2) {
        int m0 = mt1 * 16;
        #pragma unroll
        for (int nt = 0; nt < 4; nt++) {
            int col = (w * 4 + nt) * 8 + t * 2;
            *reinterpret_cast<float2*>(&g_Q[(m0 + g) * 128 + col])     = make_float2(c1[0][nt][0], c1[0][nt][1]);
            *reinterpret_cast<float2*>(&g_Q[(m0 + g + 8) * 128 + col]) = make_float2(c1[0][nt][2], c1[0][nt][3]);
            uint32_t klo = pack_h2(c1[1][nt][0], c1[1][nt][1]);
            uint32_t khi = pack_h2(c1[1][nt][2], c1[1][nt][3]);
            uint32_t vlo = pack_h2(c1[2][nt][0], c1[2][nt][1]);
            uint32_t vhi = pack_h2(c1[2][nt][2], c1[2][nt][3]);
            int j = col / 2;
            int slot = (j >> 1) * 4 + (j & 1);
            g_KV[(m0 + g) * 128 + slot]         = klo;
            g_KV[(m0 + g + 8) * 128 + slot]     = khi;
            g_KV[(m0 + g) * 128 + slot + 2]     = vlo;
            g_KV[(m0 + g + 8) * 128 + slot + 2] = vhi;
        }
    }
}

// ---------------- parallel scan, stage 1 ----------------
__global__ void __launch_bounds__(256) scan_part_kernel()
{
    __shared__ int ws[8];
    int gid = blockIdx.x * 256 + threadIdx.x;
    int v = (gid < N_NODES) ? g_cnt[gid] : 0;
    int s = __reduce_add_sync(0xffffffffu, v);
    if ((threadIdx.x & 31) == 0) ws[threadIdx.x >> 5] = s;
    __syncthreads();
    if (threadIdx.x == 0) {
        int tot = 0;
        #pragma unroll
        for (int j = 0; j < 8; j++) tot += ws[j];
        g_part[blockIdx.x] = tot;
    }
}

// ---------------- parallel scan, stage 2 ----------------
__global__ void __launch_bounds__(256) scan_final_kernel()
{
    __shared__ int ps[8];
    __shared__ int ws[8];
    const int t = threadIdx.x, b = blockIdx.x;
    const int lane = t & 31, w = t >> 5;

    int pv = (t < b) ? g_part[t] : 0;
    int psum = __reduce_add_sync(0xffffffffu, pv);
    if (lane == 0) ps[w] = psum;
    __syncthreads();
    int offset = 0;
    #pragma unroll
    for (int j = 0; j < 8; j++) offset += ps[j];

    int gid = b * 256 + t;
    int c = (gid < N_NODES) ? g_cnt[gid] : 0;
    int incl = c;
    #pragma unroll
    for (int d = 1; d < 32; d <<= 1) {
        int u = __shfl_up_sync(0xffffffffu, incl, d);
        if (lane >= d) incl += u;
    }
    if (lane == 31) ws[w] = incl;
    __syncthreads();
    int woff = 0;
    #pragma unroll
    for (int j = 0; j < 8; j++) woff += (j < w) ? ws[j] : 0;

    int excl = offset + woff + incl - c;
    if (gid < N_NODES) {
        g_row_off[gid] = excl;
        g_cnt[gid]     = excl;           // cursor for scatter
    }
    if (gid == N_NODES - 1)
        g_row_off[N_NODES] = excl + c;
}

// ---------------- aggregation: one warp per dst node, 2-edge software pipeline ----------------
// lane l owns columns 4l..4l+3; each 4-lane quad owns one head (D=16).
__global__ void __launch_bounds__(256) aggregate_kernel(float* __restrict__ out)
{
    int warp = (blockIdx.x * blockDim.x + threadIdx.x) >> 5;
    int lane = threadIdx.x & 31;
    if (warp >= N_NODES) return;
    const int node = warp;

    const float4 q = *reinterpret_cast<const float4*>(&g_Q[node * 128 + lane * 4]);
    float4 acc0 = make_float4(0.f, 0.f, 0.f, 0.f);
    float4 acc1 = make_float4(0.f, 0.f, 0.f, 0.f);
    float  zz0 = 0.f, zz1 = 0.f;

    const int beg = g_row_off[node];
    const int end = g_row_off[node + 1];
    int i = beg;

    for (; i + 2 <= end; i += 2) {
        int s0 = g_esrc[i];
        int s1 = g_esrc[i + 1];
        uint4 kv0 = *reinterpret_cast<const uint4*>(&g_KV[s0 * 128 + lane * 4]);
        uint4 kv1 = *reinterpret_cast<const uint4*>(&g_KV[s1 * 128 + lane * 4]);

        float2 k0a = __half22float2(*reinterpret_cast<__half2*>(&kv0.x));
        float2 k0b = __half22float2(*reinterpret_cast<__half2*>(&kv0.y));
        float2 k1a = __half22float2(*reinterpret_cast<__half2*>(&kv1.x));
        float2 k1b = __half22float2(*reinterpret_cast<__half2*>(&kv1.y));

        float p0 = q.x * k0a.x + q.y * k0a.y + q.z * k0b.x + q.w * k0b.y;
        float p1 = q.x * k1a.x + q.y * k1a.y + q.z * k1b.x + q.w * k1b.y;
        p0 += __shfl_xor_sync(0xffffffffu, p0, 1);
        p1 += __shfl_xor_sync(0xffffffffu, p1, 1);
        p0 += __shfl_xor_sync(0xffffffffu, p0, 2);
        p1 += __shfl_xor_sync(0xffffffffu, p1, 2);

        float w0 = __expf(fminf(fmaxf(p0 * 0.25f, -5.f), 5.f));
        float w1 = __expf(fminf(fmaxf(p1 * 0.25f, -5.f), 5.f));

        float2 v0a = __half22float2(*reinterpret_cast<__half2*>(&kv0.z));
        float2 v0b = __half22float2(*reinterpret_cast<__half2*>(&kv0.w));
        float2 v1a = __half22float2(*reinterpret_cast<__half2*>(&kv1.z));
        float2 v1b = __half22float2(*reinterpret_cast<__half2*>(&kv1.w));

        acc0.x += v0a.x * w0;  acc0.y += v0a.y * w0;
        acc0.z += v0b.x * w0;  acc0.w += v0b.y * w0;
        acc1.x += v1a.x * w1;  acc1.y += v1a.y * w1;
        acc1.z += v1b.x * w1;  acc1.w += v1b.y * w1;
        zz0 += w0;
        zz1 += w1;
    }

    if (i < end) {
        int s = g_esrc[i];
        uint4 kv = *reinterpret_cast<const uint4*>(&g_KV[s * 128 + lane * 4]);
        float2 ka = __half22float2(*reinterpret_cast<__half2*>(&kv.x));
        float2 kb = __half22float2(*reinterpret_cast<__half2*>(&kv.y));
        float p = q.x * ka.x + q.y * ka.y + q.z * kb.x + q.w * kb.y;
        p += __shfl_xor_sync(0xffffffffu, p, 1);
        p += __shfl_xor_sync(0xffffffffu, p, 2);
        float wgt = __expf(fminf(fmaxf(p * 0.25f, -5.f), 5.f));
        float2 va = __half22float2(*reinterpret_cast<__half2*>(&kv.z));
        float2 vb = __half22float2(*reinterpret_cast<__half2*>(&kv.w));
        acc0.x += va.x * wgt;  acc0.y += va.y * wgt;
        acc0.z += vb.x * wgt;  acc0.w += vb.y * wgt;
        zz0 += wgt;
    }

    float inv = 1.f / (zz0 + zz1 + 1e-6f);
    float4 o = make_float4((acc0.x + acc1.x) * inv, (acc0.y + acc1.y) * inv,
                           (acc0.z + acc1.z) * inv, (acc0.w + acc1.w) * inv);
    *reinterpret_cast<float4*>(&out[node * 128 + lane * 4]) = o;

    if (lane == 0) g_cnt[node] = 0;                 // restore invariant for next launch
}

// ---------------- launch ----------------
extern "C" void kernel_launch(void* const* d_in, const int* in_sizes, int n_in,
                              void* d_out, int out_size)
{
    const float* h   = (const float*)d_in[0];
    // d_in[1] (e), d_in[8] (We), d_in[9] (be) are unused by the reference output.
    const int*   src = (const int*)d_in[2];
    const int*   dst = (const int*)d_in[3];
    const float* Wq  = (const float*)d_in[4];
    const float* bq  = (const float*)d_in[5];
    const float* Wk  = (const float*)d_in[6];
    const float* bk  = (const float*)d_in[7];
    const float* Wv  = (const float*)d_in[10];
    const float* bv  = (const float*)d_in[11];
    float* out = (float*)d_out;

    dim3 prep_grid(M_TILES, 1, 3);  // z=0: A-frag pack (800k threads), z=1: count, z=2: B frags
    prep_kernel<<<prep_grid, 256>>>(h, dst, Wq, Wk, Wv);

    scan_part_kernel<<<SCAN_BLOCKS, 256>>>();
    scan_final_kernel<<<SCAN_BLOCKS, 256>>>();

    dim3 gs_grid(G_BLOCKS, 1, 2);   // z=0: gemm (2 m-tiles/CTA), z=1: scatter (hidden)
    gemm_scatter<<<gs_grid, 128>>>(bq, bk, bv, src, dst);

    int agg_blocks = (N_NODES + 7) / 8;   // 8 warps (nodes) per 256-thread block
    aggregate_kernel<<<agg_blocks, 256>>>(out);
}